// round 2
// baseline (speedup 1.0000x reference)
#include <cuda_runtime.h>
#include <math.h>

#define BATCH 4
#define SEQ   4096
#define CIN   128
#define CQK   32
#define COUT  128
#define PROJ  192   // 32 (K) + 32 (Q) + 128 (V')

// Scratch (device globals: no allocation allowed in kernel_launch)
__device__ float g_Wcomb[CIN * PROJ];            // [c][j] combined projection weight
__device__ float g_bcomb[PROJ];                  // combined bias (V' part includes folded GCN bias)
__device__ float g_P[BATCH * SEQ * PROJ];        // per-token projections [b*s][192]

// ---------------------------------------------------------------------------
// Kernel 0: build combined weight/bias.
//   cols 0..31  : wk rows (K proj),  bias bk
//   cols 32..63 : wq rows (Q proj),  bias bq
//   cols 64..191: W2[c][u] = sum_o wv[o][c]*weight[o][u]
//                 b2[u]    = sum_o bv[o]*weight[o][u] + bias[u]
// ---------------------------------------------------------------------------
__global__ void prep_kernel(const float* __restrict__ weight, const float* __restrict__ bias,
                            const float* __restrict__ wq, const float* __restrict__ bq,
                            const float* __restrict__ wk, const float* __restrict__ bk,
                            const float* __restrict__ wv, const float* __restrict__ bv) {
    int j = blockIdx.x;      // 0..191
    int c = threadIdx.x;     // 0..127
    float wval;
    if (j < 32) {
        wval = wk[j * CIN + c];
    } else if (j < 64) {
        wval = wq[(j - 32) * CIN + c];
    } else {
        int u = j - 64;
        float s = 0.f;
        #pragma unroll 4
        for (int o = 0; o < COUT; ++o)
            s += wv[o * CIN + c] * weight[o * COUT + u];
        wval = s;
    }
    g_Wcomb[c * PROJ + j] = wval;
    if (c == 0) {
        float bval;
        if (j < 32) bval = bk[j];
        else if (j < 64) bval = bq[j - 32];
        else {
            int u = j - 64;
            float s = 0.f;
            for (int o = 0; o < COUT; ++o) s += bv[o] * weight[o * COUT + u];
            bval = s + bias[u];
        }
        g_bcomb[j] = bval;
    }
}

// ---------------------------------------------------------------------------
// Kernel 1: projection GEMM  g_P[r][j] = x[r][:] @ g_Wcomb[:, j] + g_bcomb[j]
//   rows = BATCH*SEQ = 16384, cols = 192, K = 128
//   Tile 64x64, BK=32, 256 threads, 4x4 micro-tile.
// ---------------------------------------------------------------------------
__global__ __launch_bounds__(256) void proj_kernel(const float* __restrict__ x) {
    __shared__ float As[32][64];   // [k][m] (A transposed)
    __shared__ float Bs[32][64];   // [k][n]
    const int tid = threadIdx.x;
    const int ty = tid >> 4, tx = tid & 15;
    const int rowblk = blockIdx.x * 64;
    const int colblk = blockIdx.y * 64;

    float acc[4][4];
    #pragma unroll
    for (int i = 0; i < 4; ++i)
        #pragma unroll
        for (int j = 0; j < 4; ++j) acc[i][j] = 0.f;

    for (int kb = 0; kb < CIN; kb += 32) {
        __syncthreads();
        {   // A tile: 64 rows x 32 k, transposed into As[k][m]
            int r = tid >> 2, kg = (tid & 3) * 8;
            const float* src = x + (size_t)(rowblk + r) * CIN + kb + kg;
            float4 a0 = *(const float4*)(src);
            float4 a1 = *(const float4*)(src + 4);
            As[kg + 0][r] = a0.x; As[kg + 1][r] = a0.y; As[kg + 2][r] = a0.z; As[kg + 3][r] = a0.w;
            As[kg + 4][r] = a1.x; As[kg + 5][r] = a1.y; As[kg + 6][r] = a1.z; As[kg + 7][r] = a1.w;
        }
        {   // B tile: 32 k x 64 cols
            int k = tid >> 3, cg = (tid & 7) * 8;
            const float* src = g_Wcomb + (size_t)(kb + k) * PROJ + colblk + cg;
            *(float4*)&Bs[k][cg]     = *(const float4*)(src);
            *(float4*)&Bs[k][cg + 4] = *(const float4*)(src + 4);
        }
        __syncthreads();
        #pragma unroll
        for (int k = 0; k < 32; ++k) {
            float4 a = *(float4*)&As[k][ty * 4];
            float4 b = *(float4*)&Bs[k][tx * 4];
            float av[4] = {a.x, a.y, a.z, a.w};
            float bv[4] = {b.x, b.y, b.z, b.w};
            #pragma unroll
            for (int i = 0; i < 4; ++i)
                #pragma unroll
                for (int j = 0; j < 4; ++j) acc[i][j] += av[i] * bv[j];
        }
    }
    // epilogue: add bias, store
    #pragma unroll
    for (int i = 0; i < 4; ++i) {
        float* dst = g_P + (size_t)(rowblk + ty * 4 + i) * PROJ + colblk + tx * 4;
        float4 o;
        o.x = acc[i][0] + g_bcomb[colblk + tx * 4 + 0];
        o.y = acc[i][1] + g_bcomb[colblk + tx * 4 + 1];
        o.z = acc[i][2] + g_bcomb[colblk + tx * 4 + 2];
        o.w = acc[i][3] + g_bcomb[colblk + tx * 4 + 3];
        *(float4*)dst = o;
    }
}

// ---------------------------------------------------------------------------
// Kernel 2: flash attention
//   out[b, i, :] = sum_j softmax_j(K_i . Q_j) * V'[b, j, :]
//   BM=64 rows/CTA, BN=64 cols/tile, 256 threads.
//   Thread (ty,tx) in 16x16 grid:
//     S micro-tile: rows r0..r0+3 (r0=4*ty) x cols 4*tx..+3
//     O micro-tile: rows r0..r0+3 x cols {4*tx..+3} U {64+4*tx..+3}
//   Online softmax state (m, l) replicated across the 16 tx-lanes of a row group.
// ---------------------------------------------------------------------------
#define BM 64
#define BN 64
#define PS_LD 68   // padded row length for P tile (68*4 bytes, 16B-aligned rows)

__global__ __launch_bounds__(256, 2) void attn_kernel(float* __restrict__ out) {
    extern __shared__ float smem[];
    float* Ks = smem;                      // [32][64]  (d-major, transposed)
    float* Qs = Ks + 32 * 64;              // [32][64]
    float* Vs = Qs + 32 * 64;              // [64][128]
    float* Ps = Vs + 64 * 128;             // [64][PS_LD]

    const int tid = threadIdx.x;
    const int ty = tid >> 4, tx = tid & 15;
    const int b = blockIdx.y;
    const int iblk = blockIdx.x * BM;
    const float* Pbase = g_P + (size_t)b * SEQ * PROJ;
    const int r0 = ty * 4;

    // Load K block (rows i of this CTA), transposed -> Ks[d][r]
    {
        int r = tid >> 2, dg = (tid & 3) * 8;
        const float* src = Pbase + (size_t)(iblk + r) * PROJ + dg;
        float4 k0 = *(const float4*)(src);
        float4 k1 = *(const float4*)(src + 4);
        Ks[(dg + 0) * 64 + r] = k0.x; Ks[(dg + 1) * 64 + r] = k0.y;
        Ks[(dg + 2) * 64 + r] = k0.z; Ks[(dg + 3) * 64 + r] = k0.w;
        Ks[(dg + 4) * 64 + r] = k1.x; Ks[(dg + 5) * 64 + r] = k1.y;
        Ks[(dg + 6) * 64 + r] = k1.z; Ks[(dg + 7) * 64 + r] = k1.w;
    }

    float m_[4], l_[4], o_[4][8];
    #pragma unroll
    for (int i = 0; i < 4; ++i) {
        m_[i] = -INFINITY; l_[i] = 0.f;
        #pragma unroll
        for (int u = 0; u < 8; ++u) o_[i][u] = 0.f;
    }

    for (int jt = 0; jt < SEQ; jt += BN) {
        __syncthreads();   // previous iter's smem consumers done
        {   // Q tile transposed -> Qs[d][c]
            int c = tid >> 2, dg = (tid & 3) * 8;
            const float* src = Pbase + (size_t)(jt + c) * PROJ + 32 + dg;
            float4 q0 = *(const float4*)(src);
            float4 q1 = *(const float4*)(src + 4);
            Qs[(dg + 0) * 64 + c] = q0.x; Qs[(dg + 1) * 64 + c] = q0.y;
            Qs[(dg + 2) * 64 + c] = q0.z; Qs[(dg + 3) * 64 + c] = q0.w;
            Qs[(dg + 4) * 64 + c] = q1.x; Qs[(dg + 5) * 64 + c] = q1.y;
            Qs[(dg + 6) * 64 + c] = q1.z; Qs[(dg + 7) * 64 + c] = q1.w;
        }
        {   // V tile -> Vs[kk][u]
            int kk = tid >> 2, ug = (tid & 3) * 32;
            const float* src = Pbase + (size_t)(jt + kk) * PROJ + 64 + ug;
            float* dst = Vs + kk * 128 + ug;
            #pragma unroll
            for (int t = 0; t < 8; ++t)
                *(float4*)(dst + 4 * t) = *(const float4*)(src + 4 * t);
        }
        __syncthreads();

        // --- S = K_blk . Q_tile^T, 4x4 per thread ---
        float s[4][4];
        #pragma unroll
        for (int i = 0; i < 4; ++i)
            #pragma unroll
            for (int j = 0; j < 4; ++j) s[i][j] = 0.f;
        #pragma unroll
        for (int d = 0; d < 32; ++d) {
            float4 a = *(float4*)&Ks[d * 64 + r0];
            float4 q = *(float4*)&Qs[d * 64 + tx * 4];
            float av[4] = {a.x, a.y, a.z, a.w};
            float qv[4] = {q.x, q.y, q.z, q.w};
            #pragma unroll
            for (int i = 0; i < 4; ++i)
                #pragma unroll
                for (int j = 0; j < 4; ++j) s[i][j] += av[i] * qv[j];
        }

        // --- online softmax (per row group of 16 tx-lanes) ---
        #pragma unroll
        for (int i = 0; i < 4; ++i) {
            float rmax = fmaxf(fmaxf(s[i][0], s[i][1]), fmaxf(s[i][2], s[i][3]));
            #pragma unroll
            for (int off = 8; off >= 1; off >>= 1)
                rmax = fmaxf(rmax, __shfl_xor_sync(0xffffffffu, rmax, off));
            float mn = fmaxf(m_[i], rmax);
            float corr = __expf(m_[i] - mn);
            float4 p;
            p.x = __expf(s[i][0] - mn);
            p.y = __expf(s[i][1] - mn);
            p.z = __expf(s[i][2] - mn);
            p.w = __expf(s[i][3] - mn);
            float rsum = p.x + p.y + p.z + p.w;
            #pragma unroll
            for (int off = 8; off >= 1; off >>= 1)
                rsum += __shfl_xor_sync(0xffffffffu, rsum, off);
            l_[i] = l_[i] * corr + rsum;
            m_[i] = mn;
            #pragma unroll
            for (int u = 0; u < 8; ++u) o_[i][u] *= corr;
            *(float4*)&Ps[(r0 + i) * PS_LD + tx * 4] = p;
        }
        __syncthreads();

        // --- O += P @ V ---
        #pragma unroll 4
        for (int kk = 0; kk < BN; ++kk) {
            float4 v0 = *(float4*)&Vs[kk * 128 + tx * 4];
            float4 v1 = *(float4*)&Vs[kk * 128 + 64 + tx * 4];
            #pragma unroll
            for (int i = 0; i < 4; ++i) {
                float p = Ps[(r0 + i) * PS_LD + kk];
                o_[i][0] += p * v0.x; o_[i][1] += p * v0.y;
                o_[i][2] += p * v0.z; o_[i][3] += p * v0.w;
                o_[i][4] += p * v1.x; o_[i][5] += p * v1.y;
                o_[i][6] += p * v1.z; o_[i][7] += p * v1.w;
            }
        }
    }

    // epilogue: divide by l, store (bias already folded into V')
    #pragma unroll
    for (int i = 0; i < 4; ++i) {
        float inv = 1.f / l_[i];
        float* dst = out + ((size_t)b * SEQ + iblk + r0 + i) * COUT;
        float4 w0, w1;
        w0.x = o_[i][0] * inv; w0.y = o_[i][1] * inv; w0.z = o_[i][2] * inv; w0.w = o_[i][3] * inv;
        w1.x = o_[i][4] * inv; w1.y = o_[i][5] * inv; w1.z = o_[i][6] * inv; w1.w = o_[i][7] * inv;
        *(float4*)(dst + tx * 4)      = w0;
        *(float4*)(dst + 64 + tx * 4) = w1;
    }
}

// ---------------------------------------------------------------------------
extern "C" void kernel_launch(void* const* d_in, const int* in_sizes, int n_in,
                              void* d_out, int out_size) {
    const float* x      = (const float*)d_in[0];
    const float* weight = (const float*)d_in[1];
    const float* bias   = (const float*)d_in[2];
    const float* wq     = (const float*)d_in[3];
    const float* bq     = (const float*)d_in[4];
    const float* wk     = (const float*)d_in[5];
    const float* bk     = (const float*)d_in[6];
    const float* wv     = (const float*)d_in[7];
    const float* bv     = (const float*)d_in[8];
    float* out = (float*)d_out;

    prep_kernel<<<PROJ, CIN>>>(weight, bias, wq, bq, wk, bk, wv, bv);
    proj_kernel<<<dim3(BATCH * SEQ / 64, PROJ / 64), 256>>>(x);

    const int smem_bytes = (32 * 64 + 32 * 64 + 64 * 128 + 64 * PS_LD) * sizeof(float);
    cudaFuncSetAttribute(attn_kernel, cudaFuncAttributeMaxDynamicSharedMemorySize, smem_bytes);
    attn_kernel<<<dim3(SEQ / BM, BATCH), 256, smem_bytes>>>(out);
}

// round 11
// speedup vs baseline: 3.1536x; 3.1536x over previous
#include <cuda_runtime.h>
#include <cstdint>
#include <math.h>

#define BATCH 4
#define SEQ   4096
#define CIN   128
#define COUT  128
#define PROJ  192   // 32 (K) + 32 (Q) + 128 (V')

#define BM 128
#define BN 64
#define NT (SEQ / BN)   // 64

// ---------------- device scratch ----------------
__device__ float g_Wcomb[CIN * PROJ];
__device__ float g_bcomb[PROJ];
// g_P layout [b][s][192]: cols 0-31 K (fp32), 32-63 Q (fp32), 64-191 V' (tf32-rounded)
__device__ float g_P[BATCH * SEQ * PROJ];

__device__ __forceinline__ uint32_t tf32r(float f) {
    uint32_t u; asm("cvt.rna.tf32.f32 %0, %1;" : "=r"(u) : "f"(f)); return u;
}

// m16n8k8 tf32 mma (sm_80+ feature, legal on base sm_103 target)
#define MMA8(d, a, bb) \
    asm volatile( \
        "mma.sync.aligned.m16n8k8.row.col.f32.tf32.tf32.f32 " \
        "{%0,%1,%2,%3},{%4,%5,%6,%7},{%8,%9},{%0,%1,%2,%3};" \
        : "+f"((d)[0]), "+f"((d)[1]), "+f"((d)[2]), "+f"((d)[3]) \
        : "r"((a)[0]), "r"((a)[1]), "r"((a)[2]), "r"((a)[3]), \
          "r"((bb)[0]), "r"((bb)[1]))

#define CP_COMMIT()  asm volatile("cp.async.commit_group;" ::: "memory")
#define CP_WAIT0()   asm volatile("cp.async.wait_group 0;" ::: "memory")

__device__ __forceinline__ void cpa16(uint32_t dst, const float* src) {
    asm volatile("cp.async.cg.shared.global [%0], [%1], 16;"
                 :: "r"(dst), "l"(__cvta_generic_to_global(src)) : "memory");
}

// ---------------------------------------------------------------------------
// Kernel 0: combined weight/bias.  blocks 0..63: copy wk/wq rows.
// blocks 64..191: W2 column via smem-cached weight column.
// ---------------------------------------------------------------------------
__global__ void prep_kernel(const float* __restrict__ weight, const float* __restrict__ bias,
                            const float* __restrict__ wq, const float* __restrict__ bq,
                            const float* __restrict__ wk, const float* __restrict__ bk,
                            const float* __restrict__ wv, const float* __restrict__ bv) {
    int j = blockIdx.x;      // 0..191
    int c = threadIdx.x;     // 0..127
    if (j < 64) {
        float w = (j < 32) ? wk[j * CIN + c] : wq[(j - 32) * CIN + c];
        g_Wcomb[c * PROJ + j] = w;
        if (c == 0) g_bcomb[j] = (j < 32) ? bk[j] : bq[j - 32];
    } else {
        int u = j - 64;
        __shared__ float wcol[COUT];
        wcol[c] = weight[c * COUT + u];
        __syncthreads();
        float s0 = 0.f, s1 = 0.f, s2 = 0.f, s3 = 0.f;
        #pragma unroll 4
        for (int o = 0; o < COUT; o += 4) {
            s0 += wv[(o + 0) * CIN + c] * wcol[o + 0];
            s1 += wv[(o + 1) * CIN + c] * wcol[o + 1];
            s2 += wv[(o + 2) * CIN + c] * wcol[o + 2];
            s3 += wv[(o + 3) * CIN + c] * wcol[o + 3];
        }
        g_Wcomb[c * PROJ + j] = (s0 + s1) + (s2 + s3);
        if (c == 0) {
            float s = 0.f;
            for (int o = 0; o < COUT; ++o) s += bv[o] * wcol[o];
            g_bcomb[j] = s + bias[u];
        }
    }
}

// ---------------------------------------------------------------------------
// Kernel 1: projection GEMM.  V' columns (>=64) stored tf32-RNA-rounded.
// ---------------------------------------------------------------------------
__global__ __launch_bounds__(256) void proj_kernel(const float* __restrict__ x) {
    __shared__ float As[32][64];
    __shared__ float Bs[32][64];
    const int tid = threadIdx.x;
    const int ty = tid >> 4, tx = tid & 15;
    const int rowblk = blockIdx.x * 64;
    const int colblk = blockIdx.y * 64;
    const bool roundv = (colblk >= 64);

    float acc[4][4];
    #pragma unroll
    for (int i = 0; i < 4; ++i)
        #pragma unroll
        for (int j = 0; j < 4; ++j) acc[i][j] = 0.f;

    for (int kb = 0; kb < CIN; kb += 32) {
        __syncthreads();
        {
            int r = tid >> 2, kg = (tid & 3) * 8;
            const float* src = x + (size_t)(rowblk + r) * CIN + kb + kg;
            float4 a0 = *(const float4*)(src);
            float4 a1 = *(const float4*)(src + 4);
            As[kg + 0][r] = a0.x; As[kg + 1][r] = a0.y; As[kg + 2][r] = a0.z; As[kg + 3][r] = a0.w;
            As[kg + 4][r] = a1.x; As[kg + 5][r] = a1.y; As[kg + 6][r] = a1.z; As[kg + 7][r] = a1.w;
        }
        {
            int k = tid >> 3, cg = (tid & 7) * 8;
            const float* src = g_Wcomb + (size_t)(kb + k) * PROJ + colblk + cg;
            *(float4*)&Bs[k][cg]     = *(const float4*)(src);
            *(float4*)&Bs[k][cg + 4] = *(const float4*)(src + 4);
        }
        __syncthreads();
        #pragma unroll
        for (int k = 0; k < 32; ++k) {
            float4 a = *(float4*)&As[k][ty * 4];
            float4 b4 = *(float4*)&Bs[k][tx * 4];
            float av[4] = {a.x, a.y, a.z, a.w};
            float bw[4] = {b4.x, b4.y, b4.z, b4.w};
            #pragma unroll
            for (int i = 0; i < 4; ++i)
                #pragma unroll
                for (int j = 0; j < 4; ++j) acc[i][j] += av[i] * bw[j];
        }
    }
    #pragma unroll
    for (int i = 0; i < 4; ++i) {
        float* dst = g_P + (size_t)(rowblk + ty * 4 + i) * PROJ + colblk + tx * 4;
        float4 o;
        float v0 = acc[i][0] + g_bcomb[colblk + tx * 4 + 0];
        float v1 = acc[i][1] + g_bcomb[colblk + tx * 4 + 1];
        float v2 = acc[i][2] + g_bcomb[colblk + tx * 4 + 2];
        float v3 = acc[i][3] + g_bcomb[colblk + tx * 4 + 3];
        if (roundv) {
            o.x = __uint_as_float(tf32r(v0)); o.y = __uint_as_float(tf32r(v1));
            o.z = __uint_as_float(tf32r(v2)); o.w = __uint_as_float(tf32r(v3));
        } else {
            o.x = v0; o.y = v1; o.z = v2; o.w = v3;
        }
        *(float4*)dst = o;
    }
}

// ---------------------------------------------------------------------------
// Kernel 2: mma.sync (legacy tensor path) flash attention, no-max softmax.
//   8 warps in 4(M)x2(N) grid; BM=128 rows/CTA; 64 j-tiles of BN=64.
//   S: 3xTF32 split-precision (K,Q fp32 -> hi/lo).  PV: plain tf32.
//   Q/V: cp.async triple-buffer rings from g_P.  P: double-buffered smem.
//   One __syncthreads per tile.
// ---------------------------------------------------------------------------
// SMEM (floats): Q 3x[64][36], V 3x[64][136], P 2x[128][68], K [128][36]
#define QOFF   0
#define QBUFF  2304        // 64*36
#define VOFF   6912        // 3*2304
#define VBUFF  8704        // 64*136
#define POFF   33024       // VOFF + 3*8704
#define PBUFF  8704        // 128*68
#define KOFF   50432       // POFF + 2*8704
#define SMTOT_F 55040      // KOFF + 128*36
#define SMTOT_B (SMTOT_F * 4)   // 220160 bytes

__global__ __launch_bounds__(256, 1) void attn_kernel(float* __restrict__ out) {
    extern __shared__ __align__(16) float sm[];
    const int tid = threadIdx.x;
    const int wid = tid >> 5, lane = tid & 31;
    const int g = lane >> 2, tq = lane & 3;
    const int wm = wid & 3, wn = wid >> 2;
    const int b = blockIdx.y, iblk = blockIdx.x * BM;
    const float* gP = g_P + (size_t)b * SEQ * PROJ;

    float* Qs = sm + QOFF;
    float* Vs = sm + VOFF;
    float* Ps = sm + POFF;
    float* Ks = sm + KOFF;

    // ---- cp.async issue for tile t: Q[64][32] + V[64][128] from g_P ----
    auto issueQV = [&](int t) {
        int jt = t * BN;
        int r = tid >> 2;
        {
            int c = (tid & 3) * 8;
            float* d = &Qs[(t % 3) * QBUFF + r * 36 + c];
            const float* s = gP + (size_t)(jt + r) * PROJ + 32 + c;
            cpa16((uint32_t)__cvta_generic_to_shared(d), s);
            cpa16((uint32_t)__cvta_generic_to_shared(d + 4), s + 4);
        }
        {
            int cb = (tid & 3) * 32;
            #pragma unroll
            for (int i = 0; i < 8; ++i) {
                int c = cb + 4 * i;
                float* d = &Vs[(t % 3) * VBUFF + r * 136 + c];
                const float* s = gP + (size_t)(jt + r) * PROJ + 64 + c;
                cpa16((uint32_t)__cvta_generic_to_shared(d), s);
            }
        }
    };

    issueQV(0);
    CP_COMMIT();

    // K block -> smem [128][36] (fp32)
    {
        int r = tid >> 1, c0 = (tid & 1) * 16;
        #pragma unroll
        for (int i = 0; i < 4; ++i) {
            float4 v = *(const float4*)(gP + (size_t)(iblk + r) * PROJ + c0 + 4 * i);
            *(float4*)&Ks[r * 36 + c0 + 4 * i] = v;
        }
    }
    CP_WAIT0();
    __syncthreads();

    // K fragments, hi/lo split.  A frag m16k8: a0[g][t] a1[g+8][t] a2[g][t+4] a3[g+8][t+4]
    uint32_t khi[2][4][4], klo[2][4][4];
    #pragma unroll
    for (int m = 0; m < 2; ++m)
        #pragma unroll
        for (int k = 0; k < 4; ++k) {
            int r = 32 * wm + 16 * m, k0 = 8 * k;
            float f[4];
            f[0] = Ks[(r + g) * 36 + k0 + tq];
            f[1] = Ks[(r + g + 8) * 36 + k0 + tq];
            f[2] = Ks[(r + g) * 36 + k0 + tq + 4];
            f[3] = Ks[(r + g + 8) * 36 + k0 + tq + 4];
            #pragma unroll
            for (int i = 0; i < 4; ++i) {
                uint32_t h = tf32r(f[i]);
                khi[m][k][i] = h;
                klo[m][k][i] = tf32r(f[i] - __uint_as_float(h));
            }
        }

    float o[2][8][4];
    #pragma unroll
    for (int m = 0; m < 2; ++m)
        #pragma unroll
        for (int n = 0; n < 8; ++n)
            #pragma unroll
            for (int i = 0; i < 4; ++i) o[m][n][i] = 0.f;
    float lsum[4] = {0.f, 0.f, 0.f, 0.f};

    for (int t = 0; t < NT; ++t) {
        if (t + 1 < NT) { issueQV(t + 1); CP_COMMIT(); }

        // ---- S = K @ Q^T  (3xTF32 split) ----
        float s[2][4][4];
        #pragma unroll
        for (int m = 0; m < 2; ++m)
            #pragma unroll
            for (int n = 0; n < 4; ++n)
                #pragma unroll
                for (int i = 0; i < 4; ++i) s[m][n][i] = 0.f;

        const float* Qb = Qs + (t % 3) * QBUFF;
        #pragma unroll
        for (int k = 0; k < 4; ++k) {
            int k0 = 8 * k;
            uint32_t bhi[4][2], blo[4][2];
            #pragma unroll
            for (int n = 0; n < 4; ++n) {
                int qr = 32 * wn + 8 * n + g;
                float q0 = Qb[qr * 36 + k0 + tq];
                float q1 = Qb[qr * 36 + k0 + tq + 4];
                uint32_t h0 = tf32r(q0), h1 = tf32r(q1);
                bhi[n][0] = h0; bhi[n][1] = h1;
                blo[n][0] = tf32r(q0 - __uint_as_float(h0));
                blo[n][1] = tf32r(q1 - __uint_as_float(h1));
            }
            #pragma unroll
            for (int m = 0; m < 2; ++m)
                #pragma unroll
                for (int n = 0; n < 4; ++n) {
                    MMA8(s[m][n], klo[m][k], bhi[n]);
                    MMA8(s[m][n], khi[m][k], blo[n]);
                    MMA8(s[m][n], khi[m][k], bhi[n]);
                }
        }

        // ---- exp + row-sum + P store (tf32) ----
        float* Pb = Ps + (t & 1) * PBUFF;
        #pragma unroll
        for (int m = 0; m < 2; ++m)
            #pragma unroll
            for (int n = 0; n < 4; ++n) {
                float p0 = __expf(s[m][n][0]), p1 = __expf(s[m][n][1]);
                float p2 = __expf(s[m][n][2]), p3 = __expf(s[m][n][3]);
                lsum[2 * m + 0] += p0 + p1;
                lsum[2 * m + 1] += p2 + p3;
                int r = 32 * wm + 16 * m + g, c = 32 * wn + 8 * n + 2 * tq;
                *(uint2*)&Pb[r * 68 + c]       = make_uint2(tf32r(p0), tf32r(p1));
                *(uint2*)&Pb[(r + 8) * 68 + c] = make_uint2(tf32r(p2), tf32r(p3));
            }

        CP_WAIT0();
        __syncthreads();   // P exchange + Q/V(t+1) visibility

        // ---- O += P @ V ----
        const float* Vb = Vs + (t % 3) * VBUFF;
        #pragma unroll
        for (int k = 0; k < 8; ++k) {
            int k0 = 8 * k;
            uint32_t af[2][4];
            #pragma unroll
            for (int m = 0; m < 2; ++m) {
                int r = 32 * wm + 16 * m;
                af[m][0] = __float_as_uint(Pb[(r + g) * 68 + k0 + tq]);
                af[m][1] = __float_as_uint(Pb[(r + g + 8) * 68 + k0 + tq]);
                af[m][2] = __float_as_uint(Pb[(r + g) * 68 + k0 + tq + 4]);
                af[m][3] = __float_as_uint(Pb[(r + g + 8) * 68 + k0 + tq + 4]);
            }
            uint32_t vb[8][2];
            #pragma unroll
            for (int n = 0; n < 8; ++n) {
                int u = 64 * wn + 8 * n + g;
                vb[n][0] = __float_as_uint(Vb[(k0 + tq) * 136 + u]);
                vb[n][1] = __float_as_uint(Vb[(k0 + tq + 4) * 136 + u]);
            }
            #pragma unroll
            for (int m = 0; m < 2; ++m)
                #pragma unroll
                for (int n = 0; n < 8; ++n)
                    MMA8(o[m][n], af[m], vb[n]);
        }
    }

    // ---- epilogue: reduce l across quad + warp columns, scale, store ----
    #pragma unroll
    for (int i = 0; i < 4; ++i) {
        lsum[i] += __shfl_xor_sync(0xffffffffu, lsum[i], 1);
        lsum[i] += __shfl_xor_sync(0xffffffffu, lsum[i], 2);
    }
    float* lred = Ks;   // reuse K region: [2][128]
    if (tq == 0) {
        #pragma unroll
        for (int m = 0; m < 2; ++m) {
            lred[wn * 128 + 32 * wm + 16 * m + g]     = lsum[2 * m + 0];
            lred[wn * 128 + 32 * wm + 16 * m + g + 8] = lsum[2 * m + 1];
        }
    }
    __syncthreads();
    #pragma unroll
    for (int m = 0; m < 2; ++m) {
        int r = 32 * wm + 16 * m;
        float inv0 = 1.f / (lred[r + g]     + lred[128 + r + g]);
        float inv1 = 1.f / (lred[r + g + 8] + lred[128 + r + g + 8]);
        #pragma unroll
        for (int n = 0; n < 8; ++n) {
            int u = 64 * wn + 8 * n + 2 * tq;
            float2 w0 = make_float2(o[m][n][0] * inv0, o[m][n][1] * inv0);
            float2 w1 = make_float2(o[m][n][2] * inv1, o[m][n][3] * inv1);
            *(float2*)&out[((size_t)b * SEQ + iblk + r + g) * COUT + u]     = w0;
            *(float2*)&out[((size_t)b * SEQ + iblk + r + g + 8) * COUT + u] = w1;
        }
    }
}

// ---------------------------------------------------------------------------
extern "C" void kernel_launch(void* const* d_in, const int* in_sizes, int n_in,
                              void* d_out, int out_size) {
    const float* x      = (const float*)d_in[0];
    const float* weight = (const float*)d_in[1];
    const float* bias   = (const float*)d_in[2];
    const float* wq     = (const float*)d_in[3];
    const float* bq     = (const float*)d_in[4];
    const float* wk     = (const float*)d_in[5];
    const float* bk     = (const float*)d_in[6];
    const float* wv     = (const float*)d_in[7];
    const float* bv     = (const float*)d_in[8];
    float* out = (float*)d_out;

    prep_kernel<<<PROJ, CIN>>>(weight, bias, wq, bq, wk, bk, wv, bv);
    proj_kernel<<<dim3(BATCH * SEQ / 64, PROJ / 64), 256>>>(x);

    cudaFuncSetAttribute(attn_kernel, cudaFuncAttributeMaxDynamicSharedMemorySize, SMTOT_B);
    attn_kernel<<<dim3(SEQ / BM, BATCH), 256, SMTOT_B>>>(out);
}